// round 8
// baseline (speedup 1.0000x reference)
#include <cuda_runtime.h>
#include <cstdint>

#define BATCH   8192
#define FEAT    128
#define DEG     32
#define KSEL    16
#define EMB     128

// ---------------- scratch (static device arrays; no allocation) ----------------
__device__ float g_xbuf[BATCH * FEAT];          // self feats   [B,128]
__device__ float g_agg [3 * BATCH * FEAT];      // agg feats    [3,B,128]
__device__ float g_cs0 [BATCH];                 // center class-0 score

// ---------------- f32x2 packed-FMA helpers (Blackwell FFMA2 via PTX) ----------------
__device__ __forceinline__ unsigned long long pk2(float x, float y) {
    unsigned int xu = __float_as_uint(x), yu = __float_as_uint(y);
    unsigned long long r;
    asm("mov.b64 %0, {%1, %2};" : "=l"(r) : "r"(xu), "r"(yu));
    return r;
}
__device__ __forceinline__ void upk2(unsigned long long v, float& x, float& y) {
    unsigned int lo, hi;
    asm("mov.b64 {%0, %1}, %2;" : "=r"(lo), "=r"(hi) : "l"(v));
    x = __uint_as_float(lo);
    y = __uint_as_float(hi);
}
__device__ __forceinline__ void ffma2(unsigned long long& d,
                                      unsigned long long a,
                                      unsigned long long b) {
    asm("fma.rn.f32x2 %0, %1, %2, %0;" : "+l"(d) : "l"(a), "l"(b));
}

// ---------------- Kernel A: self gather + center scores (1 warp per node) ----------------
__global__ __launch_bounds__(256) void self_score_kernel(const float* __restrict__ feat,
                                                         const float* __restrict__ Wclf,
                                                         const float* __restrict__ bclf,
                                                         const int*   __restrict__ nodes,
                                                         float* __restrict__ out_cs) {
    int wg = threadIdx.x >> 5, l = threadIdx.x & 31;
    int b = blockIdx.x * 8 + wg;
    long base = (long)__ldg(nodes + b) * FEAT;
    float4 f = __ldg((const float4*)(feat + base) + l);
    *(float4*)(g_xbuf + b * FEAT + 4 * l) = f;
    // Wclf is [128,2] row-major; lane l covers rows 4l..4l+3
    float4 wAB0 = __ldg((const float4*)Wclf + 2 * l);      // rows 4l,4l+1 (cols 0,1 interleaved)
    float4 wAB1 = __ldg((const float4*)Wclf + 2 * l + 1);  // rows 4l+2,4l+3
    float p0 = f.x * wAB0.x + f.y * wAB0.z + f.z * wAB1.x + f.w * wAB1.z;
    float p1 = f.x * wAB0.y + f.y * wAB0.w + f.z * wAB1.y + f.w * wAB1.w;
    #pragma unroll
    for (int o = 16; o; o >>= 1) {
        p0 += __shfl_xor_sync(0xffffffffu, p0, o);
        p1 += __shfl_xor_sync(0xffffffffu, p1, o);
    }
    if (l == 0) {
        float c0 = p0 + __ldg(bclf);
        out_cs[b * 2]     = c0;
        out_cs[b * 2 + 1] = p1 + __ldg(bclf + 1);
        g_cs0[b] = c0;
    }
}

// ---------------- Kernel B: neighbor gather + score + top-K select + mean ----------------
// One block per (b, rel). 128 threads. All 8 row-gathers per warp issued
// back-to-back (MLP=8); the 8 shuffle-reduction chains are interleaved
// level-by-level so their latency overlaps.
__global__ __launch_bounds__(128) void agg_kernel(const float* __restrict__ feat,
                                                  const float* __restrict__ Wclf,
                                                  const float* __restrict__ bclf,
                                                  const int*   __restrict__ n1,
                                                  const int*   __restrict__ n2,
                                                  const int*   __restrict__ n3) {
    const int b   = blockIdx.x;
    const int rel = blockIdx.y;
    const int* nb = (rel == 0) ? n1 : (rel == 1) ? n2 : n3;

    __shared__ float    sf[DEG][132];   // pitch 132 avoids bank conflicts
    __shared__ float    sscore[DEG];
    __shared__ unsigned smask;

    int t = threadIdx.x;
    int w = t >> 5, l = t & 31;

    // W_clf column 0 pieces for this lane's float4 slot (rows 4l..4l+3)
    float w00 = __ldg(Wclf + 8 * l);
    float w01 = __ldg(Wclf + 8 * l + 2);
    float w02 = __ldg(Wclf + 8 * l + 4);
    float w03 = __ldg(Wclf + 8 * l + 6);
    float bias0 = __ldg(bclf);
    float cs0 = g_cs0[b];

    // phase 1: all indices, then all rows — maximal MLP
    int nidx[8];
    #pragma unroll
    for (int r = 0; r < 8; r++)
        nidx[r] = __ldg(nb + b * DEG + w + 4 * r);
    float4 f[8];
    #pragma unroll
    for (int r = 0; r < 8; r++)
        f[r] = __ldg((const float4*)(feat + (long)nidx[r] * FEAT) + l);

    // phase 2: smem store + per-lane partial dot
    float p[8];
    #pragma unroll
    for (int r = 0; r < 8; r++) {
        int n = w + 4 * r;
        *(float4*)&sf[n][4 * l] = f[r];
        p[r] = f[r].x * w00 + f[r].y * w01 + f[r].z * w02 + f[r].w * w03;
    }
    // interleaved butterfly reductions (8 independent chains per level)
    #pragma unroll
    for (int o = 16; o; o >>= 1) {
        #pragma unroll
        for (int r = 0; r < 8; r++)
            p[r] += __shfl_xor_sync(0xffffffffu, p[r], o);
    }
    if (l == 0) {
        #pragma unroll
        for (int r = 0; r < 8; r++)
            sscore[w + 4 * r] = p[r] + bias0;
    }
    __syncthreads();

    // rank-based selection of the K smallest |score - cs0| (index tiebreak
    // matches jax.lax.top_k's stable lower-index-first semantics)
    if (t < DEG) {
        float di = fabsf(sscore[t] - cs0);
        int rank = 0;
        #pragma unroll
        for (int j = 0; j < DEG; j++) {
            float dj = fabsf(sscore[j] - cs0);
            rank += (dj < di) || (dj == di && j < t);
        }
        unsigned m = __ballot_sync(0xffffffffu, rank < KSEL);
        if (t == 0) smask = m;
    }
    __syncthreads();

    unsigned m = smask;
    float sum = 0.f;
    #pragma unroll
    for (int n = 0; n < DEG; n++)
        if (m & (1u << n)) sum += sf[n][t];
    g_agg[((long)rel * BATCH + b) * FEAT + t] = sum * (1.0f / KSEL);
}

// ---------------- Kernel C: fused 3x intra GEMM + comb GEMM + relu + transpose ----------------
// 128 blocks, BM=64, 256 threads. A-tiles smem-resident; W staged through a
// DOUBLE-BUFFERED smem tile with register prefetch -> one barrier per chunk,
// L2 latency fully hidden. Inner product: packed f32x2 FMA (FFMA2).

#define APITCH 132   // smem row pitch (floats)

__device__ __forceinline__ void mma_chunk(const float* __restrict__ A,
                                          const float* __restrict__ sW,
                                          int c0, unsigned long long acc[4][4]) {
    #pragma unroll
    for (int q = 0; q < 4; q++) {
        float4 a0 = *(const float4*)&A[0 * APITCH + 4 * q];
        float4 a1 = *(const float4*)&A[1 * APITCH + 4 * q];
        float4 a2 = *(const float4*)&A[2 * APITCH + 4 * q];
        float4 a3 = *(const float4*)&A[3 * APITCH + 4 * q];
        float av0[4] = {a0.x, a0.y, a0.z, a0.w};
        float av1[4] = {a1.x, a1.y, a1.z, a1.w};
        float av2[4] = {a2.x, a2.y, a2.z, a2.w};
        float av3[4] = {a3.x, a3.y, a3.z, a3.w};
        #pragma unroll
        for (int k = 0; k < 4; k++) {
            int k2 = 4 * q + k;
            ulonglong2 b01 = *(const ulonglong2*)&sW[k2 * 128 + c0];
            ulonglong2 b23 = *(const ulonglong2*)&sW[k2 * 128 + c0 + 4];
            unsigned long long ap;
            ap = pk2(av0[k], av0[k]);
            ffma2(acc[0][0], ap, b01.x); ffma2(acc[0][1], ap, b01.y);
            ffma2(acc[0][2], ap, b23.x); ffma2(acc[0][3], ap, b23.y);
            ap = pk2(av1[k], av1[k]);
            ffma2(acc[1][0], ap, b01.x); ffma2(acc[1][1], ap, b01.y);
            ffma2(acc[1][2], ap, b23.x); ffma2(acc[1][3], ap, b23.y);
            ap = pk2(av2[k], av2[k]);
            ffma2(acc[2][0], ap, b01.x); ffma2(acc[2][1], ap, b01.y);
            ffma2(acc[2][2], ap, b23.x); ffma2(acc[2][3], ap, b23.y);
            ap = pk2(av3[k], av3[k]);
            ffma2(acc[3][0], ap, b01.x); ffma2(acc[3][1], ap, b01.y);
            ffma2(acc[3][2], ap, b23.x); ffma2(acc[3][3], ap, b23.y);
        }
    }
}

__device__ __forceinline__ void ldw(const float* __restrict__ W, int kk, int tid,
                                    float4& v0, float4& v1) {
    v0 = __ldg((const float4*)(W + kk * 128) + tid);
    v1 = __ldg((const float4*)(W + kk * 128) + tid + 256);
}
__device__ __forceinline__ void stw(float* __restrict__ sW, int tid,
                                    float4 v0, float4 v1) {
    *(float4*)&sW[tid * 4]         = v0;
    *(float4*)&sW[(tid + 256) * 4] = v1;
}

__global__ __launch_bounds__(256, 1) void fused_gemm_kernel(const float* __restrict__ Wi1,
                                                            const float* __restrict__ Wi2,
                                                            const float* __restrict__ Wi3,
                                                            const float* __restrict__ Wc,
                                                            float* __restrict__ out) {
    extern __shared__ float smem[];
    float* sSelf = smem;                               // 64*APITCH
    float* sAgg0 = smem + 64 * APITCH;
    float* sAgg1 = smem + 2 * 64 * APITCH;
    float* sAgg2 = smem + 3 * 64 * APITCH;
    float* sWb0  = smem + 4 * 64 * APITCH;             // 16*128 double buffer
    float* sWb1  = sWb0 + 16 * 128;
    float* sAggs[3] = {sAgg0, sAgg1, sAgg2};
    float* sWbuf[2] = {sWb0, sWb1};

    const int tid = threadIdx.x;
    const int bm  = blockIdx.x * 64;

    // load self tile (64x128) — 8 float4 per thread, coalesced
    #pragma unroll
    for (int i = 0; i < 8; i++) {
        int e = tid + i * 256;        // float4 index
        int row = e >> 5;             // 32 float4 per row
        int c4  = e & 31;
        float4 v = __ldg((const float4*)(g_xbuf + (long)(bm + row) * FEAT) + c4);
        *(float4*)&sSelf[row * APITCH + c4 * 4] = v;
    }
    // load agg tiles
    #pragma unroll
    for (int rel = 0; rel < 3; rel++) {
        #pragma unroll
        for (int i = 0; i < 8; i++) {
            int e = tid + i * 256;
            int row = e >> 5;
            int c4  = e & 31;
            float4 v = __ldg((const float4*)(g_agg + ((long)rel * BATCH + bm + row) * FEAT) + c4);
            *(float4*)&sAggs[rel][row * APITCH + c4 * 4] = v;
        }
    }
    __syncthreads();

    // thread micro-tile: 4 rows x 8 cols (4 f32x2 pairs). lanes span cols ->
    // A-reads are 2-address broadcasts within a warp.
    const int colg = tid & 15, rowg = tid >> 4;
    const int r0 = rowg * 4, c0 = colg * 8;

    // ---- three intra GEMMs: E_r = relu([self || agg_r] @ W_r), overwrite agg_r ----
    #pragma unroll 1
    for (int rel = 0; rel < 3; rel++) {
        const float* W = (rel == 0) ? Wi1 : (rel == 1) ? Wi2 : Wi3;
        unsigned long long acc[4][4];
        #pragma unroll
        for (int i = 0; i < 4; i++)
            #pragma unroll
            for (int j = 0; j < 4; j++) acc[i][j] = 0ull;

        float4 w0, w1;
        ldw(W, 0, tid, w0, w1);
        #pragma unroll 1
        for (int ck = 0; ck < 16; ck++) {           // 16 chunks of K=16
            float* buf = sWbuf[ck & 1];
            stw(buf, tid, w0, w1);
            __syncthreads();
            if (ck < 15) ldw(W, (ck + 1) * 16, tid, w0, w1);
            int kk = ck * 16;
            const float* A = (kk < 128) ? (sSelf + r0 * APITCH + kk)
                                        : (sAggs[rel] + r0 * APITCH + (kk - 128));
            mma_chunk(A, buf, c0, acc);
        }
        __syncthreads();   // all reads of agg_r done before overwrite
        #pragma unroll
        for (int i = 0; i < 4; i++)
            #pragma unroll
            for (int j = 0; j < 4; j++) {
                float x, y;
                upk2(acc[i][j], x, y);
                float2 v = make_float2(fmaxf(x, 0.f), fmaxf(y, 0.f));
                *(float2*)&sAggs[rel][(r0 + i) * APITCH + c0 + 2 * j] = v;
            }
        __syncthreads();
    }

    // ---- comb GEMM: relu([self||E1||E2||E3] @ Wc), write transposed [128, B] ----
    unsigned long long acc[4][4];
    #pragma unroll
    for (int i = 0; i < 4; i++)
        #pragma unroll
        for (int j = 0; j < 4; j++) acc[i][j] = 0ull;

    float4 w0, w1;
    ldw(Wc, 0, tid, w0, w1);
    #pragma unroll 1
    for (int ck = 0; ck < 32; ck++) {               // 32 chunks of K=16
        float* buf = sWbuf[ck & 1];
        stw(buf, tid, w0, w1);
        __syncthreads();
        if (ck < 31) ldw(Wc, (ck + 1) * 16, tid, w0, w1);
        int kk = ck * 16;
        const float* A;
        if (kk < 128) A = sSelf + r0 * APITCH + kk;
        else          A = sAggs[(kk - 128) >> 7] + r0 * APITCH + ((kk - 128) & 127);
        mma_chunk(A, buf, c0, acc);
    }
    // unpack, relu, transpose-store: 4 consecutive rows per column -> float4
    float f[4][8];
    #pragma unroll
    for (int i = 0; i < 4; i++)
        #pragma unroll
        for (int j = 0; j < 4; j++)
            upk2(acc[i][j], f[i][2 * j], f[i][2 * j + 1]);
    #pragma unroll
    for (int jj = 0; jj < 8; jj++) {
        float4 v = make_float4(fmaxf(f[0][jj], 0.f), fmaxf(f[1][jj], 0.f),
                               fmaxf(f[2][jj], 0.f), fmaxf(f[3][jj], 0.f));
        *(float4*)(out + (long)(c0 + jj) * BATCH + bm + r0) = v;
    }
}

// ---------------- launch ----------------
extern "C" void kernel_launch(void* const* d_in, const int* in_sizes, int n_in,
                              void* d_out, int out_size) {
    const float* feat  = (const float*)d_in[0];
    const float* Wclf  = (const float*)d_in[1];
    const float* bclf  = (const float*)d_in[2];
    const float* Wi1   = (const float*)d_in[3];
    const float* Wi2   = (const float*)d_in[4];
    const float* Wi3   = (const float*)d_in[5];
    const float* Wc    = (const float*)d_in[6];
    const int*   nodes = (const int*)d_in[7];
    const int*   n1    = (const int*)d_in[8];
    const int*   n2    = (const int*)d_in[9];
    const int*   n3    = (const int*)d_in[10];

    float* out    = (float*)d_out;
    float* out_cs = out + (long)EMB * BATCH;   // center_scores after combined

    self_score_kernel<<<BATCH / 8, 256>>>(feat, Wclf, bclf, nodes, out_cs);

    dim3 gridB(BATCH, 3);
    agg_kernel<<<gridB, 128>>>(feat, Wclf, bclf, n1, n2, n3);

    int smemC = (4 * 64 * APITCH + 2 * 16 * 128) * sizeof(float);  // ~151 KB
    cudaFuncSetAttribute(fused_gemm_kernel,
                         cudaFuncAttributeMaxDynamicSharedMemorySize, smemC);
    fused_gemm_kernel<<<BATCH / 64, 256, smemC>>>(Wi1, Wi2, Wi3, Wc, out);
}